// round 9
// baseline (speedup 1.0000x reference)
#include <cuda_runtime.h>

// Problem constants (fixed by setup_inputs)
#define S_LEN 4096
#define BATCH 8
#define DIM 1024
#define SPLIT 49
#define SCALE 32.0f           // sqrt(1024)

// R8 ticket scheme + 256-bit global accesses (Blackwell ld/st.global.v8.f32).
//
// Thread d owns a 32B chunk: col8 = d & 127 (8 floats), h = d >> 7 selects
// row parity within a pair. Unit = half-token (4 batch rows), processed as
// 2 iterations of 2 rows. One LDG.256 outstanding per warp -> 256B in flight
// per warp, 48 warps/SM x 256B = 12KB/SM > ~11.5KB needed to saturate DRAM,
// WITHOUT front-batching multiple queue entries (which regressed in R5).
//
// Ticket invariant: P (tickets pulled per launch) = N_UNITS = 8192 = 2^13
// regardless of EW_BLOCKS, so (ticket & 8191) sweeps 0..8191 every launch
// with no reset -> single graph node.
#define EW_BLOCKS 887          // +1 doc block = 888 = 148 SMs x 6 CTAs
#define N_UNITS (S_LEN * 2)    // 8192, power of two

__device__ unsigned g_ticket;  // monotonically increasing across launches

struct F8 { float v[8]; };

__device__ __forceinline__ F8 ldg256(const float* p) {
    F8 r;
    asm("ld.global.v8.f32 {%0,%1,%2,%3,%4,%5,%6,%7}, [%8];"
        : "=f"(r.v[0]), "=f"(r.v[1]), "=f"(r.v[2]), "=f"(r.v[3]),
          "=f"(r.v[4]), "=f"(r.v[5]), "=f"(r.v[6]), "=f"(r.v[7])
        : "l"(p));
    return r;
}

__device__ __forceinline__ F8 ldg256_cs(const float* p) {
    F8 r;
    asm("ld.global.cs.v8.f32 {%0,%1,%2,%3,%4,%5,%6,%7}, [%8];"
        : "=f"(r.v[0]), "=f"(r.v[1]), "=f"(r.v[2]), "=f"(r.v[3]),
          "=f"(r.v[4]), "=f"(r.v[5]), "=f"(r.v[6]), "=f"(r.v[7])
        : "l"(p));
    return r;
}

__device__ __forceinline__ void stg256_cs(float* p, const F8& r) {
    asm volatile("st.global.cs.v8.f32 [%0], {%1,%2,%3,%4,%5,%6,%7,%8};"
        :: "l"(p),
           "f"(r.v[0]), "f"(r.v[1]), "f"(r.v[2]), "f"(r.v[3]),
           "f"(r.v[4]), "f"(r.v[5]), "f"(r.v[6]), "f"(r.v[7])
        : "memory");
}

__device__ __forceinline__ void process_unit(int u, int col8, int h,
                                             const float* __restrict__ emb,
                                             const float* __restrict__ pe,
                                             float* __restrict__ out)
{
    const int t  = u >> 1;
    const int b0 = (u & 1) * 4;

    const F8 p = ldg256(pe + t * DIM + col8 * 8);   // shared by both halves

    #pragma unroll
    for (int j = 0; j < 2; j++) {
        const int row = b0 + 2 * j + h;
        const long off = (long)(t * BATCH + row) * DIM + col8 * 8;
        F8 e = ldg256_cs(emb + off);
        F8 o;
        #pragma unroll
        for (int k = 0; k < 8; k++)
            o.v[k] = fmaf(e.v[k], SCALE, p.v[k]);
        stg256_cs(out + off, o);
    }
}

__global__ __launch_bounds__(256, 6)
void pe_fused_kernel(const float* __restrict__ emb,
                     const int*   __restrict__ src,
                     const float* __restrict__ pe,
                     float*       __restrict__ out,
                     float*       __restrict__ doc)
{
    const int blk = blockIdx.x;

    if (blk > 0) {
        const int col8 = threadIdx.x & 127;
        const int h    = threadIdx.x >> 7;

        __shared__ int s_next;
        int u = blk - 1;                     // static first unit

        if (threadIdx.x == 0)
            s_next = (int)(atomicAdd(&g_ticket, 1u) & (N_UNITS - 1)) + EW_BLOCKS;
        __syncthreads();

        while (u < N_UNITS) {
            int nxt = s_next;
            __syncthreads();                 // all read s_next before overwrite
            if (threadIdx.x == 0 && nxt < N_UNITS)
                s_next = (int)(atomicAdd(&g_ticket, 1u) & (N_UNITS - 1)) + EW_BLOCKS;

            process_unit(u, col8, h, emb, pe, out);

            __syncthreads();                 // s_next for next iter is ready
            u = nxt;
        }
        return;
    }

    // ---- doc scan block (blockIdx 0, first wave, overlapped) ----
    __shared__ unsigned words[BATCH * 128];  // 4096 bits per column

    const int warp = threadIdx.x >> 5;       // batch column 0..7
    const int lane = threadIdx.x & 31;

    // Pass 1: build flag bitmasks
    #pragma unroll 8
    for (int c = 0; c < 128; c++) {
        const int t = c * 32 + lane;
        const int v = __ldg(&src[t * BATCH + warp]);
        unsigned m = __ballot_sync(0xFFFFFFFFu, v == SPLIT);
        if (lane == 0) words[warp * 128 + c] = m;
    }
    __syncwarp();

    // Pass 2: inclusive popc-scan with carry; zero positions whose next
    // position is a split token.
    int carry = 0;
    const unsigned le_mask = 0xFFFFFFFFu >> (31 - lane);
    for (int c = 0; c < 128; c++) {
        const unsigned m = words[warp * 128 + c];
        const int t = c * 32 + lane;
        const int incl = carry + __popc(m & le_mask);

        unsigned next_bit;
        if (lane < 31)
            next_bit = (m >> (lane + 1)) & 1u;
        else
            next_bit = (c < 127) ? (words[warp * 128 + c + 1] & 1u) : 0u;

        doc[t * BATCH + warp] = next_bit ? 0.0f : (float)incl;
        carry += __popc(m);
    }
}

extern "C" void kernel_launch(void* const* d_in, const int* in_sizes, int n_in,
                              void* d_out, int out_size)
{
    const float* emb = (const float*)d_in[0];   // [S, B, DIM] f32
    const int*   src = (const int*)  d_in[1];   // [S, B, 1]   i32
    const float* pe  = (const float*)d_in[2];   // [5000, 1, DIM] f32

    float* out = (float*)d_out;                  // first in_sizes[0] floats
    float* doc = out + (size_t)in_sizes[0];      // then S*B floats

    pe_fused_kernel<<<EW_BLOCKS + 1, 256>>>(emb, src, pe, out, doc);
}

// round 10
// speedup vs baseline: 1.0805x; 1.0805x over previous
#include <cuda_runtime.h>

// Problem constants (fixed by setup_inputs)
#define S_LEN 4096
#define BATCH 8
#define DIM 1024
#define D4 (DIM / 4)           // 256 float4 per row
#define SPLIT 49
#define SCALE 32.0f            // sqrt(1024)

// Per-WARP dynamic ticket distribution (R8's block-level tickets coupled all
// 8 warps via __syncthreads at every unit boundary; this removes that).
//
//   blockIdx 0        : doc segmented-count scan (first wave, fully hidden)
//   blockIdx 1..1183  : 8 independent warps each: static unit, then
//                       atomic-ticket units until out-of-range.
//
// Work unit = quarter-token (2 batch rows), 16384 units. EW warps = 9464.
// Ticket u = (counter & 16383) + 9464; in-range iff masked < 6920.
// Fixed point: pulls/launch P = W + I = 9464 + 6920 = 16384 = mask window,
// so every launch sweeps units 9464..16383 exactly once with a monotonic
// counter — no reset node, single kernel graph node, deterministic output.
//
// Inner loop keeps the proven interleaved float4 ldcs->fma->stcs shape at
// 32 regs / occ 8 (64 warps/SM). Front-batching loads regressed in R5/R9.
#define EW_BLOCKS 1183
#define EW_WARPS (EW_BLOCKS * 8)   // 9464
#define N_UNITS (S_LEN * 4)        // 16384, power of two

__device__ unsigned g_ticket;      // monotonically increasing across launches

__device__ __forceinline__ int pull_ticket() {
    unsigned v = 0;
    if ((threadIdx.x & 31) == 0)
        v = atomicAdd(&g_ticket, 1u);
    v = __shfl_sync(0xFFFFFFFFu, v, 0);
    return (int)(v & (N_UNITS - 1)) + EW_WARPS;
}

__device__ __forceinline__ void process_unit(int u, int lane,
                                             const float4* __restrict__ emb,
                                             const float4* __restrict__ pe,
                                             float4* __restrict__ out)
{
    const int t  = u >> 2;
    const int b0 = (u & 3) << 1;              // rows b0, b0+1
    const int rowA = (t * BATCH + b0) * D4;   // float4 index of row b0
    const int peRow = t * D4;

    #pragma unroll
    for (int i = 0; i < 8; i++) {
        const int c = lane + 32 * i;          // float4 column 0..255
        const float4 p = __ldg(&pe[peRow + c]);

        {   // row b0
            const int idx = rowA + c;
            float4 e = __ldcs(&emb[idx]);
            float4 o;
            o.x = fmaf(e.x, SCALE, p.x);
            o.y = fmaf(e.y, SCALE, p.y);
            o.z = fmaf(e.z, SCALE, p.z);
            o.w = fmaf(e.w, SCALE, p.w);
            __stcs(&out[idx], o);
        }
        {   // row b0+1
            const int idx = rowA + D4 + c;
            float4 e = __ldcs(&emb[idx]);
            float4 o;
            o.x = fmaf(e.x, SCALE, p.x);
            o.y = fmaf(e.y, SCALE, p.y);
            o.z = fmaf(e.z, SCALE, p.z);
            o.w = fmaf(e.w, SCALE, p.w);
            __stcs(&out[idx], o);
        }
    }
}

__global__ __launch_bounds__(256, 8)
void pe_fused_kernel(const float4* __restrict__ emb,
                     const int*    __restrict__ src,
                     const float4* __restrict__ pe,
                     float4*       __restrict__ out,
                     float*        __restrict__ doc)
{
    const int blk = blockIdx.x;

    if (blk > 0) {
        const int lane = threadIdx.x & 31;
        int u = (blk - 1) * 8 + (threadIdx.x >> 5);   // static unit 0..9463

        while (u < N_UNITS) {
            process_unit(u, lane, emb, pe, out);
            u = pull_ticket();     // stops after first out-of-range ticket
        }
        return;
    }

    // ---- doc scan block (blockIdx 0, first wave, overlapped) ----
    __shared__ unsigned words[BATCH * 128];  // 4096 bits per column

    const int warp = threadIdx.x >> 5;       // batch column 0..7
    const int lane = threadIdx.x & 31;

    // Pass 1: build flag bitmasks
    #pragma unroll 8
    for (int c = 0; c < 128; c++) {
        const int t = c * 32 + lane;
        const int v = __ldg(&src[t * BATCH + warp]);
        unsigned m = __ballot_sync(0xFFFFFFFFu, v == SPLIT);
        if (lane == 0) words[warp * 128 + c] = m;
    }
    __syncwarp();

    // Pass 2: inclusive popc-scan with carry; zero positions whose next
    // position is a split token.
    int carry = 0;
    const unsigned le_mask = 0xFFFFFFFFu >> (31 - lane);
    for (int c = 0; c < 128; c++) {
        const unsigned m = words[warp * 128 + c];
        const int t = c * 32 + lane;
        const int incl = carry + __popc(m & le_mask);

        unsigned next_bit;
        if (lane < 31)
            next_bit = (m >> (lane + 1)) & 1u;
        else
            next_bit = (c < 127) ? (words[warp * 128 + c + 1] & 1u) : 0u;

        doc[t * BATCH + warp] = next_bit ? 0.0f : (float)incl;
        carry += __popc(m);
    }
}

extern "C" void kernel_launch(void* const* d_in, const int* in_sizes, int n_in,
                              void* d_out, int out_size)
{
    const float* emb = (const float*)d_in[0];   // [S, B, DIM] f32
    const int*   src = (const int*)  d_in[1];   // [S, B, 1]   i32
    const float* pe  = (const float*)d_in[2];   // [5000, 1, DIM] f32

    float* out = (float*)d_out;                  // first in_sizes[0] floats
    float* doc = out + (size_t)in_sizes[0];      // then S*B floats

    pe_fused_kernel<<<EW_BLOCKS + 1, 256>>>(
        (const float4*)emb, src, (const float4*)pe,
        (float4*)out, doc);
}

// round 11
// speedup vs baseline: 1.1726x; 1.0853x over previous
#include <cuda_runtime.h>

// Problem constants (fixed by setup_inputs)
#define S_LEN 4096
#define BATCH 8
#define DIM 1024
#define D4 (DIM / 4)           // 256 float4 per row
#define SPLIT 49
#define SCALE 32.0f            // sqrt(1024)

// R8 (block-level dynamic tickets — best known: 42.3us kernel, 68.9% DRAM)
// with two refinements:
//   1. ONE __syncthreads per unit instead of two, via a double-buffered
//      ticket slot s_next[2] (parity flip). The end-of-iteration sync both
//      publishes the prefetched ticket and retires the slot overwritten next.
//   2. Quarter-token units (2 batch rows, 16384 units) — finer tail balance
//      at the same per-block sync count (~14).
//
// Ticket fixed point: every ew block pulls 1 initial + 1 per in-range ticket
// and stops at its first out-of-range one -> pulls/launch =
// 1183 + (16384-1183) = 16384 = 2^14 = mask window. A monotonic counter with
// (v & 16383) therefore sweeps units 1183..16383 exactly once per launch:
// no reset node, single kernel graph node, deterministic output.
#define EW_BLOCKS 1183
#define N_UNITS (S_LEN * 4)    // 16384, power of two

__device__ unsigned g_ticket;  // monotonically increasing across launches

__device__ __forceinline__ void process_unit(int u, int d,
                                             const float4* __restrict__ emb,
                                             const float4* __restrict__ pe,
                                             float4* __restrict__ out)
{
    const int t  = u >> 2;
    const int b0 = (u & 3) << 1;             // rows b0, b0+1
    const float4 p = __ldg(&pe[t * D4 + d]);

    const int idx0 = (t * BATCH + b0) * D4 + d;
    {
        float4 e = __ldcs(&emb[idx0]);
        float4 o;
        o.x = fmaf(e.x, SCALE, p.x);
        o.y = fmaf(e.y, SCALE, p.y);
        o.z = fmaf(e.z, SCALE, p.z);
        o.w = fmaf(e.w, SCALE, p.w);
        __stcs(&out[idx0], o);
    }
    {
        const int idx1 = idx0 + D4;
        float4 e = __ldcs(&emb[idx1]);
        float4 o;
        o.x = fmaf(e.x, SCALE, p.x);
        o.y = fmaf(e.y, SCALE, p.y);
        o.z = fmaf(e.z, SCALE, p.z);
        o.w = fmaf(e.w, SCALE, p.w);
        __stcs(&out[idx1], o);
    }
}

__global__ __launch_bounds__(256, 8)
void pe_fused_kernel(const float4* __restrict__ emb,
                     const int*    __restrict__ src,
                     const float4* __restrict__ pe,
                     float4*       __restrict__ out,
                     float*        __restrict__ doc)
{
    const int blk = blockIdx.x;

    if (blk > 0) {
        const int d = threadIdx.x;           // 0..255

        __shared__ int s_next[2];
        int u = blk - 1;                     // static first unit
        int parity = 0;

        if (threadIdx.x == 0)
            s_next[0] = (int)(atomicAdd(&g_ticket, 1u) & (N_UNITS - 1)) + EW_BLOCKS;
        __syncthreads();

        while (u < N_UNITS) {
            const int nxt = s_next[parity];
            // Prefetch into the OTHER slot; published by the sync below.
            if (threadIdx.x == 0 && nxt < N_UNITS)
                s_next[parity ^ 1] =
                    (int)(atomicAdd(&g_ticket, 1u) & (N_UNITS - 1)) + EW_BLOCKS;

            process_unit(u, d, emb, pe, out);

            __syncthreads();                 // single barrier per unit
            u = nxt;
            parity ^= 1;
        }
        return;
    }

    // ---- doc scan block (blockIdx 0, first wave, overlapped) ----
    __shared__ unsigned words[BATCH * 128];  // 4096 bits per column

    const int warp = threadIdx.x >> 5;       // batch column 0..7
    const int lane = threadIdx.x & 31;

    // Pass 1: build flag bitmasks
    #pragma unroll 8
    for (int c = 0; c < 128; c++) {
        const int t = c * 32 + lane;
        const int v = __ldg(&src[t * BATCH + warp]);
        unsigned m = __ballot_sync(0xFFFFFFFFu, v == SPLIT);
        if (lane == 0) words[warp * 128 + c] = m;
    }
    __syncwarp();

    // Pass 2: inclusive popc-scan with carry; zero positions whose next
    // position is a split token.
    int carry = 0;
    const unsigned le_mask = 0xFFFFFFFFu >> (31 - lane);
    for (int c = 0; c < 128; c++) {
        const unsigned m = words[warp * 128 + c];
        const int t = c * 32 + lane;
        const int incl = carry + __popc(m & le_mask);

        unsigned next_bit;
        if (lane < 31)
            next_bit = (m >> (lane + 1)) & 1u;
        else
            next_bit = (c < 127) ? (words[warp * 128 + c + 1] & 1u) : 0u;

        doc[t * BATCH + warp] = next_bit ? 0.0f : (float)incl;
        carry += __popc(m);
    }
}

extern "C" void kernel_launch(void* const* d_in, const int* in_sizes, int n_in,
                              void* d_out, int out_size)
{
    const float* emb = (const float*)d_in[0];   // [S, B, DIM] f32
    const int*   src = (const int*)  d_in[1];   // [S, B, 1]   i32
    const float* pe  = (const float*)d_in[2];   // [5000, 1, DIM] f32

    float* out = (float*)d_out;                  // first in_sizes[0] floats
    float* doc = out + (size_t)in_sizes[0];      // then S*B floats

    pe_fused_kernel<<<EW_BLOCKS + 1, 256>>>(
        (const float4*)emb, src, (const float4*)pe,
        (float4*)out, doc);
}

// round 12
// speedup vs baseline: 1.1750x; 1.0020x over previous
#include <cuda_runtime.h>

// Problem constants (fixed by setup_inputs)
#define S_LEN 4096
#define BATCH 8
#define DIM 1024
#define D4 (DIM / 4)           // 256 float4 per row
#define SPLIT 49
#define SCALE 32.0f            // sqrt(1024)

// Synthesis of the two verified wins:
//   - R8 decomposition: HALF-TOKEN units (4 batch rows, 8192 units),
//     block-level dynamic tickets (absorbs between-SM L2-die variance),
//     interleaved float4 ldcs->fma->stcs inner loop at 32 regs / occ 8.
//   - R11 ticket plumbing: double-buffered slot s_next[2] -> ONE
//     __syncthreads per unit (~7 barriers/block instead of ~14).
//
// Ticket fixed point: each ew block pulls 1 initial + 1 per in-range ticket,
// stopping at its first out-of-range one -> pulls/launch =
// 1183 + (8192-1183) = 8192 = 2^13 = mask window. A monotonic counter with
// (v & 8191) therefore sweeps units 1183..8191 exactly once per launch:
// no reset node, single kernel graph node, deterministic output.
#define EW_BLOCKS 1183
#define N_UNITS (S_LEN * 2)    // 8192, power of two

__device__ unsigned g_ticket;  // monotonically increasing across launches

__device__ __forceinline__ void process_unit(int u, int d,
                                             const float4* __restrict__ emb,
                                             const float4* __restrict__ pe,
                                             float4* __restrict__ out)
{
    const int t  = u >> 1;
    const int b0 = (u & 1) * 4;              // rows b0 .. b0+3
    const float4 p = __ldg(&pe[t * D4 + d]);

    #pragma unroll
    for (int b = b0; b < b0 + 4; b++) {
        const int idx = (t * BATCH + b) * D4 + d;
        float4 e = __ldcs(&emb[idx]);
        float4 o;
        o.x = fmaf(e.x, SCALE, p.x);
        o.y = fmaf(e.y, SCALE, p.y);
        o.z = fmaf(e.z, SCALE, p.z);
        o.w = fmaf(e.w, SCALE, p.w);
        __stcs(&out[idx], o);
    }
}

__global__ __launch_bounds__(256, 8)
void pe_fused_kernel(const float4* __restrict__ emb,
                     const int*    __restrict__ src,
                     const float4* __restrict__ pe,
                     float4*       __restrict__ out,
                     float*        __restrict__ doc)
{
    const int blk = blockIdx.x;

    if (blk > 0) {
        const int d = threadIdx.x;           // 0..255

        __shared__ int s_next[2];
        int u = blk - 1;                     // static first unit
        int parity = 0;

        if (threadIdx.x == 0)
            s_next[0] = (int)(atomicAdd(&g_ticket, 1u) & (N_UNITS - 1)) + EW_BLOCKS;
        __syncthreads();

        while (u < N_UNITS) {
            const int nxt = s_next[parity];
            // Prefetch into the OTHER slot; published by the sync below.
            if (threadIdx.x == 0 && nxt < N_UNITS)
                s_next[parity ^ 1] =
                    (int)(atomicAdd(&g_ticket, 1u) & (N_UNITS - 1)) + EW_BLOCKS;

            process_unit(u, d, emb, pe, out);

            __syncthreads();                 // single barrier per unit
            u = nxt;
            parity ^= 1;
        }
        return;
    }

    // ---- doc scan block (blockIdx 0, first wave, overlapped) ----
    __shared__ unsigned words[BATCH * 128];  // 4096 bits per column

    const int warp = threadIdx.x >> 5;       // batch column 0..7
    const int lane = threadIdx.x & 31;

    // Pass 1: build flag bitmasks
    #pragma unroll 8
    for (int c = 0; c < 128; c++) {
        const int t = c * 32 + lane;
        const int v = __ldg(&src[t * BATCH + warp]);
        unsigned m = __ballot_sync(0xFFFFFFFFu, v == SPLIT);
        if (lane == 0) words[warp * 128 + c] = m;
    }
    __syncwarp();

    // Pass 2: inclusive popc-scan with carry; zero positions whose next
    // position is a split token.
    int carry = 0;
    const unsigned le_mask = 0xFFFFFFFFu >> (31 - lane);
    for (int c = 0; c < 128; c++) {
        const unsigned m = words[warp * 128 + c];
        const int t = c * 32 + lane;
        const int incl = carry + __popc(m & le_mask);

        unsigned next_bit;
        if (lane < 31)
            next_bit = (m >> (lane + 1)) & 1u;
        else
            next_bit = (c < 127) ? (words[warp * 128 + c + 1] & 1u) : 0u;

        doc[t * BATCH + warp] = next_bit ? 0.0f : (float)incl;
        carry += __popc(m);
    }
}

extern "C" void kernel_launch(void* const* d_in, const int* in_sizes, int n_in,
                              void* d_out, int out_size)
{
    const float* emb = (const float*)d_in[0];   // [S, B, DIM] f32
    const int*   src = (const int*)  d_in[1];   // [S, B, 1]   i32
    const float* pe  = (const float*)d_in[2];   // [5000, 1, DIM] f32

    float* out = (float*)d_out;                  // first in_sizes[0] floats
    float* doc = out + (size_t)in_sizes[0];      // then S*B floats

    pe_fused_kernel<<<EW_BLOCKS + 1, 256>>>(
        (const float4*)emb, src, (const float4*)pe,
        (float4*)out, doc);
}